// round 4
// baseline (speedup 1.0000x reference)
#include <cuda_runtime.h>
#include <cuda_bf16.h>
#include <cstdint>

#define N_ROIS   32768
#define N_GT     1024
#define N_IMAGES 8
#define NTHREADS 256
#define CNT_BLOCKS 32            // counting / scatter blocks
#define N_WARPS_TOT 256          // CNT_BLOCKS * 8

// -------- device globals (no allocation allowed) --------
__device__ int4   g_wcntp[N_WARPS_TOT];   // packed 8x16-bit per-warp per-batch ROI counts
__device__ int    g_perm[N_ROIS];         // permuted-order -> original ROI index
__device__ int    g_roff[N_IMAGES + 1];   // ROI batch offsets (permuted space)
__device__ float4 g_cbox[N_GT];           // GT: x1, y1, x2+1, y2+1 (stable order in batch)
__device__ float  g_carea[N_GT];          // GT area
__device__ float  g_clab[N_GT];           // GT label
__device__ int    g_off[N_IMAGES + 1];    // GT batch offsets

__device__ __forceinline__ int unpack16(const int4& v, int b) {
    const int* p = reinterpret_cast<const int*>(&v);
    return (p[b >> 1] >> ((b & 1) * 16)) & 0xffff;
}

// ---------------------------------------------------------------------------
// Kernel A: per-warp per-batch ROI counts (grid 32 x 256). Each thread: 4 ROIs.
// Scalar loads only (input buffers are not 16B-aligned).
// ---------------------------------------------------------------------------
__global__ void __launch_bounds__(NTHREADS) count_kernel(const int* __restrict__ rb) {
    int t = blockIdx.x * NTHREADS + threadIdx.x;           // 0..8191
    int v0 = rb[4 * t + 0];
    int v1 = rb[4 * t + 1];
    int v2 = rb[4 * t + 2];
    int v3 = rb[4 * t + 3];
    unsigned s[8];
#pragma unroll
    for (int w = 0; w < 8; w++) {
        unsigned c = (unsigned)((v0 == w) + (v1 == w) + (v2 == w) + (v3 == w));
        s[w] = __reduce_add_sync(0xffffffffu, c);
    }
    if ((threadIdx.x & 31) == 0) {
        int gw = t >> 5;
        int4 p;
        p.x = (int)(s[0] | (s[1] << 16));
        p.y = (int)(s[2] | (s[3] << 16));
        p.z = (int)(s[4] | (s[5] << 16));
        p.w = (int)(s[6] | (s[7] << 16));
        g_wcntp[gw] = p;
    }
}

// ---------------------------------------------------------------------------
// Kernel C: blocks 0..31 scatter the ROI permutation (deterministic, no atomics);
// block 32 writes g_roff and does stable GT bucketing.
// ---------------------------------------------------------------------------
__global__ void __launch_bounds__(NTHREADS) scatter_kernel(const int* __restrict__ rb,
                                                           const float* __restrict__ gt,
                                                           const int* __restrict__ gb) {
    __shared__ int4 sping[NTHREADS];
    __shared__ int4 spong[NTHREADS];
    __shared__ int  sroff[N_IMAGES + 1];
    __shared__ int  swb[8][8];          // running per-warp per-batch bases
    __shared__ int  sgb[N_GT];          // staged GT batch indices (block 32)
    __shared__ int  sgcnt[8];
    __shared__ int  sgoff[N_IMAGES + 1];

    const int tid = threadIdx.x;

    // ---- inclusive scan of packed per-warp counts (all blocks) ----
    sping[tid] = g_wcntp[tid];
    __syncthreads();
    int4* src = sping;
    int4* dst = spong;
#pragma unroll
    for (int d = 1; d < NTHREADS; d <<= 1) {
        int4 v = src[tid];
        if (tid >= d) {
            int4 u = src[tid - d];
            v.x += u.x; v.y += u.y; v.z += u.z; v.w += u.w;
        }
        dst[tid] = v;
        __syncthreads();
        int4* tmp = src; src = dst; dst = tmp;
    }
    // src[tid] = inclusive scan; src[255] = totals per batch
    if (tid == 0) {
        int4 tot = src[NTHREADS - 1];
        int o = 0;
        for (int b = 0; b < N_IMAGES; b++) { sroff[b] = o; o += unpack16(tot, b); }
        sroff[N_IMAGES] = o;
    }
    __syncthreads();

    if (blockIdx.x < CNT_BLOCKS) {
        // ---- scatter block: warp bases ----
        if (tid < 64) {
            int wl = tid >> 3, b = tid & 7;
            int gw = blockIdx.x * 8 + wl;
            int excl = (gw > 0) ? unpack16(src[gw - 1], b) : 0;
            swb[wl][b] = sroff[b] + excl;
        }
        __syncthreads();

        int t = blockIdx.x * NTHREADS + tid;
        int vb[4];
        vb[0] = rb[4 * t + 0];
        vb[1] = rb[4 * t + 1];
        vb[2] = rb[4 * t + 2];
        vb[3] = rb[4 * t + 3];
        const int wl = tid >> 5, lane = tid & 31;
        const unsigned lt = (1u << lane) - 1u;
#pragma unroll
        for (int r = 0; r < 4; r++) {
            int b = vb[r];
            unsigned m = __match_any_sync(0xffffffffu, b);
            int rank = __popc(m & lt);
            int base = swb[wl][b];
            __syncwarp();
            if ((m & lt) == 0)                      // leader of this batch group
                swb[wl][b] = base + __popc(m);
            __syncwarp();
            g_perm[base + rank] = 4 * t + r;
        }
    } else {
        // ---- block 32: write g_roff + GT bucketing ----
        if (tid <= N_IMAGES) g_roff[tid] = sroff[tid];

        for (int j = tid; j < N_GT; j += NTHREADS) sgb[j] = gb[j];
        __syncthreads();

        const int w = tid >> 5, lane = tid & 31;
        int cnt = 0;
        for (int j0 = 0; j0 < N_GT; j0 += 32) {
            int bb = sgb[j0 + lane];
            unsigned m = __ballot_sync(0xffffffffu, bb == w);
            cnt += __popc(m);
        }
        if (lane == 0) sgcnt[w] = cnt;
        __syncthreads();
        if (tid == 0) {
            int o = 0;
            for (int b = 0; b < N_IMAGES; b++) { sgoff[b] = o; o += sgcnt[b]; }
            sgoff[N_IMAGES] = o;
            for (int b = 0; b <= N_IMAGES; b++) g_off[b] = sgoff[b];
        }
        __syncthreads();

        int pos = sgoff[w];
        for (int j0 = 0; j0 < N_GT; j0 += 32) {
            int j = j0 + lane;
            int bb = sgb[j];
            bool mine = (bb == w);
            unsigned m = __ballot_sync(0xffffffffu, mine);
            if (mine) {
                int idx = pos + __popc(m & ((1u << lane) - 1u));
                const float* p = gt + 5 * j;
                float x1 = p[0], y1 = p[1], x2 = p[2], y2 = p[3], cls = p[4];
                g_cbox[idx]  = make_float4(x1, y1, x2 + 1.0f, y2 + 1.0f);
                g_carea[idx] = ((x2 - x1) + 1.0f) * ((y2 - y1) + 1.0f);
                g_clab[idx]  = cls;
            }
            pos += __popc(m);
        }
    }
}

// ---------------------------------------------------------------------------
// Kernel D: main. Threads process ROIs in batch-sorted order; all lanes in a
// warp share a batch -> broadcast smem reads, uniform bounds. 4 independent
// argmax chains break the recurrence.
// ---------------------------------------------------------------------------
#define IOU_STEP(J, BI, BU, BJ) {                               \
    float4 g  = sbox[J];                                        \
    float ag  = sarea[J];                                       \
    float iw  = fminf(rx2p, g.z) - fmaxf(rx1, g.x);             \
    float ih  = fminf(ry2p, g.w) - fmaxf(ry1, g.y);             \
    float inter = fmaxf(iw, 0.0f) * ih;                         \
    float uni   = (area_r + ag) - inter;                        \
    bool better = inter * (BU) > (BI) * uni;                    \
    BI = better ? inter : (BI);                                 \
    BU = better ? uni   : (BU);                                 \
    BJ = better ? (J)   : (BJ);                                 \
}

__global__ void __launch_bounds__(NTHREADS) roitarget_kernel(const float* __restrict__ rois,
                                                             float* __restrict__ out) {
    __shared__ float4 sbox[N_GT];
    __shared__ float  sarea[N_GT];
    __shared__ int    sroff[N_IMAGES + 1];
    __shared__ int    sgoff[N_IMAGES + 1];
    __shared__ int    sblo, sbhi;

    const int tid = threadIdx.x;
    if (tid <= N_IMAGES) { sroff[tid] = g_roff[tid]; sgoff[tid] = g_off[tid]; }
    __syncthreads();

    const int pos = blockIdx.x * NTHREADS + tid;
    int b = 0;
#pragma unroll
    for (int k = 1; k < N_IMAGES; k++) b += (pos >= sroff[k]);

    if (tid == 0) sblo = b;
    if (tid == NTHREADS - 1) sbhi = b;
    __syncthreads();

    // load only this block's GT window into shared
    const int gbase = sgoff[sblo];
    const int gend  = sgoff[sbhi + 1];
    for (int j = gbase + tid; j < gend; j += NTHREADS) {
        sbox[j - gbase]  = g_cbox[j];
        sarea[j - gbase] = g_carea[j];
    }
    __syncthreads();

    const int i = g_perm[pos];
    const float* r = rois + 5 * i;
    const float rx1 = __ldg(r + 0), ry1 = __ldg(r + 1);
    const float rx2 = __ldg(r + 2), ry2 = __ldg(r + 3);
    const float rx2p = rx2 + 1.0f;
    const float ry2p = ry2 + 1.0f;
    const float ew = (rx2 - rx1) + 1.0f;
    const float eh = (ry2 - ry1) + 1.0f;
    const float area_r = ew * eh;

    const int j0 = sgoff[b] - gbase;
    const int j1 = sgoff[b + 1] - gbase;

    float bi0 = 0.0f, bu0 = 1.0f; int bj0 = -1;
    float bi1 = 0.0f, bu1 = 1.0f; int bj1 = -1;
    float bi2 = 0.0f, bu2 = 1.0f; int bj2 = -1;
    float bi3 = 0.0f, bu3 = 1.0f; int bj3 = -1;

    int j = j0;
    for (; j + 4 <= j1; j += 4) {
        IOU_STEP(j + 0, bi0, bu0, bj0);
        IOU_STEP(j + 1, bi1, bu1, bj1);
        IOU_STEP(j + 2, bi2, bu2, bj2);
        IOU_STEP(j + 3, bi3, bu3, bj3);
    }
    for (; j < j1; ++j) {
        IOU_STEP(j, bi0, bu0, bj0);
    }

    // merge chains: total order (iou desc, j asc) -> first-occurrence argmax
    float bi = bi0, bu = bu0; int bj = bj0;
    {
        float a = bi1 * bu, c = bi * bu1;
        bool take = (a > c) || (a == c && (unsigned)bj1 < (unsigned)bj);
        if (take) { bi = bi1; bu = bu1; bj = bj1; }
    }
    {
        float a = bi2 * bu, c = bi * bu2;
        bool take = (a > c) || (a == c && (unsigned)bj2 < (unsigned)bj);
        if (take) { bi = bi2; bu = bu2; bj = bj2; }
    }
    {
        float a = bi3 * bu, c = bi * bu3;
        bool take = (a > c) || (a == c && (unsigned)bj3 < (unsigned)bj);
        if (take) { bi = bi3; bu = bu3; bj = bj3; }
    }

    const float iou = bi / bu;
    const bool  fg  = (bj >= 0) && (iou >= 0.5f);

    float lbl = 0.0f, dx = 0.0f, dy = 0.0f, dw = 0.0f, dh = 0.0f, wgt = 0.0f;
    if (fg) {
        float4 g = sbox[bj];
        float gw  = g.z - g.x;                  // (x2+1) - x1
        float gh  = g.w - g.y;
        float gcx = g.x + 0.5f * gw;
        float gcy = g.y + 0.5f * gh;
        float ecx = rx1 + 0.5f * ew;
        float ecy = ry1 + 0.5f * eh;
        dx = (gcx - ecx) / ew;
        dy = (gcy - ecy) / eh;
        dw = logf(gw / ew);
        dh = logf(gh / eh);
        lbl = g_clab[gbase + bj];
        wgt = 1.0f;
    }

    // Layout: labels[N] | deltas[N][4] | bbwgts[N][1]
    out[i] = lbl;
    reinterpret_cast<float4*>(out + N_ROIS)[i] = make_float4(dx, dy, dw, dh);
    out[N_ROIS * 5 + i] = wgt;
}

extern "C" void kernel_launch(void* const* d_in, const int* in_sizes, int n_in,
                              void* d_out, int out_size) {
    const float* rois = (const float*)d_in[0];
    const int*   rb   = (const int*)d_in[1];
    const float* gt   = (const float*)d_in[2];
    const int*   gb   = (const int*)d_in[3];
    float* out = (float*)d_out;

    count_kernel<<<CNT_BLOCKS, NTHREADS>>>(rb);
    scatter_kernel<<<CNT_BLOCKS + 1, NTHREADS>>>(rb, gt, gb);
    roitarget_kernel<<<N_ROIS / NTHREADS, NTHREADS>>>(rois, out);
}

// round 5
// speedup vs baseline: 1.2183x; 1.2183x over previous
#include <cuda_runtime.h>
#include <cuda_bf16.h>
#include <cstdint>

#define N_ROIS   32768
#define N_GT     1024
#define N_IMAGES 8
#define NTHREADS 256
#define NBLOCKS  (N_ROIS / NTHREADS)   // 128

// ---------------------------------------------------------------------------
// Single fused kernel:
//   Phase 1: per-block stable GT bucketing (batch-compacted) into shared mem
//   Phase 2: block-local ROI sort by batch (deterministic, ballot-based)
//   Phase 3: per-ROI division-free argmax IoU (4 independent chains) + deltas
// ---------------------------------------------------------------------------
#define IOU_STEP(J, BI, BU, BJ) {                               \
    float4 g  = sbox[J];                                        \
    float ag  = sarea[J];                                       \
    float iw  = fminf(rx2p, g.z) - fmaxf(rx1, g.x);             \
    float ih  = fminf(ry2p, g.w) - fmaxf(ry1, g.y);             \
    float inter = fmaxf(iw, 0.0f) * ih;                         \
    float uni   = (area_r + ag) - inter;                        \
    bool better = inter * (BU) > (BI) * uni;                    \
    BI = better ? inter : (BI);                                 \
    BU = better ? uni   : (BU);                                 \
    BJ = better ? (J)   : (BJ);                                 \
}

__global__ void __launch_bounds__(NTHREADS) roitarget_fused(const float* __restrict__ rois,
                                                            const int* __restrict__ rb,
                                                            const float* __restrict__ gt,
                                                            const int* __restrict__ gb,
                                                            float* __restrict__ out) {
    __shared__ float4 sbox[N_GT];          // 16KB: x1, y1, x2+1, y2+1 (batch-compacted)
    __shared__ float  sarea[N_GT];         // 4KB
    __shared__ float  slab[N_GT];          // 4KB
    __shared__ int    sgb[N_GT];           // 4KB staged gt batch ids
    __shared__ int    sgcnt[N_IMAGES];
    __shared__ int    sgoff[N_IMAGES + 1];
    __shared__ int    swc[8][8];           // per-warp per-batch ROI counts
    __shared__ int    wbase[8][8];         // scatter bases
    __shared__ int    ssrc[NTHREADS];      // sorted pos -> original ROI index
    __shared__ int    ssb[NTHREADS];       // sorted pos -> batch

    const int tid  = threadIdx.x;
    const int w    = tid >> 5;
    const int lane = tid & 31;
    const unsigned lt = (1u << lane) - 1u;

    // ---------------- Phase 1: GT bucketing (stable within batch) ----------
    for (int j = tid; j < N_GT; j += NTHREADS) sgb[j] = gb[j];
    __syncthreads();

    // warp w owns batch w: count
    {
        int cnt = 0;
        for (int j0 = 0; j0 < N_GT; j0 += 32) {
            int bb = sgb[j0 + lane];
            unsigned m = __ballot_sync(0xffffffffu, bb == w);
            cnt += __popc(m);
        }
        if (lane == 0) sgcnt[w] = cnt;
    }
    __syncthreads();
    if (tid == 0) {
        int o = 0;
        for (int b = 0; b < N_IMAGES; b++) { sgoff[b] = o; o += sgcnt[b]; }
        sgoff[N_IMAGES] = o;
    }
    __syncthreads();

    {
        int pos = sgoff[w];
        for (int j0 = 0; j0 < N_GT; j0 += 32) {
            int j = j0 + lane;
            int bb = sgb[j];
            bool mine = (bb == w);
            unsigned m = __ballot_sync(0xffffffffu, mine);
            if (mine) {
                int idx = pos + __popc(m & lt);
                const float* p = gt + 5 * j;
                float x1 = p[0], y1 = p[1], x2 = p[2], y2 = p[3], cls = p[4];
                sbox[idx]  = make_float4(x1, y1, x2 + 1.0f, y2 + 1.0f);
                sarea[idx] = ((x2 - x1) + 1.0f) * ((y2 - y1) + 1.0f);
                slab[idx]  = cls;
            }
            pos += __popc(m);
        }
    }

    // ---------------- Phase 2: block-local ROI sort by batch ---------------
    const int i = blockIdx.x * NTHREADS + tid;
    const int myb = rb[i];
    int myrank = 0;
#pragma unroll
    for (int bb = 0; bb < N_IMAGES; bb++) {
        unsigned m = __ballot_sync(0xffffffffu, myb == bb);
        if (myb == bb) myrank = __popc(m & lt);
        if (lane == 0) swc[w][bb] = __popc(m);
    }
    __syncthreads();
    if (tid < 64) {
        int ww = tid >> 3, bb = tid & 7;
        int o = 0;
        for (int b2 = 0; b2 < bb; b2++)
#pragma unroll
            for (int w2 = 0; w2 < 8; w2++) o += swc[w2][b2];
        for (int w2 = 0; w2 < ww; w2++) o += swc[w2][bb];
        wbase[ww][bb] = o;
    }
    __syncthreads();
    {
        int dest = wbase[w][myb] + myrank;
        ssrc[dest] = i;
        ssb[dest]  = myb;
    }
    __syncthreads();

    // ---------------- Phase 3: argmax IoU + regression ---------------------
    const int ii = ssrc[tid];
    const int b  = ssb[tid];
    const float* r = rois + 5 * ii;
    const float rx1 = __ldg(r + 0), ry1 = __ldg(r + 1);
    const float rx2 = __ldg(r + 2), ry2 = __ldg(r + 3);
    const float rx2p = rx2 + 1.0f;
    const float ry2p = ry2 + 1.0f;
    const float ew = (rx2 - rx1) + 1.0f;
    const float eh = (ry2 - ry1) + 1.0f;
    const float area_r = ew * eh;

    const int j0 = sgoff[b];
    const int j1 = sgoff[b + 1];

    float bi0 = 0.0f, bu0 = 1.0f; int bj0 = -1;
    float bi1 = 0.0f, bu1 = 1.0f; int bj1 = -1;
    float bi2 = 0.0f, bu2 = 1.0f; int bj2 = -1;
    float bi3 = 0.0f, bu3 = 1.0f; int bj3 = -1;

    int j = j0;
    for (; j + 4 <= j1; j += 4) {
        IOU_STEP(j + 0, bi0, bu0, bj0);
        IOU_STEP(j + 1, bi1, bu1, bj1);
        IOU_STEP(j + 2, bi2, bu2, bj2);
        IOU_STEP(j + 3, bi3, bu3, bj3);
    }
    for (; j < j1; ++j) {
        IOU_STEP(j, bi0, bu0, bj0);
    }

    // merge chains: total order (iou desc, j asc) -> first-occurrence argmax
    float bi = bi0, bu = bu0; int bj = bj0;
    {
        float a = bi1 * bu, c = bi * bu1;
        bool take = (a > c) || (a == c && (unsigned)bj1 < (unsigned)bj);
        if (take) { bi = bi1; bu = bu1; bj = bj1; }
    }
    {
        float a = bi2 * bu, c = bi * bu2;
        bool take = (a > c) || (a == c && (unsigned)bj2 < (unsigned)bj);
        if (take) { bi = bi2; bu = bu2; bj = bj2; }
    }
    {
        float a = bi3 * bu, c = bi * bu3;
        bool take = (a > c) || (a == c && (unsigned)bj3 < (unsigned)bj);
        if (take) { bi = bi3; bu = bu3; bj = bj3; }
    }

    const float iou = bi / bu;
    const bool  fg  = (bj >= 0) && (iou >= 0.5f);

    float lbl = 0.0f, dx = 0.0f, dy = 0.0f, dw = 0.0f, dh = 0.0f, wgt = 0.0f;
    if (fg) {
        float4 g = sbox[bj];
        float gw  = g.z - g.x;                  // (x2+1) - x1
        float gh  = g.w - g.y;
        float gcx = g.x + 0.5f * gw;
        float gcy = g.y + 0.5f * gh;
        float ecx = rx1 + 0.5f * ew;
        float ecy = ry1 + 0.5f * eh;
        dx = (gcx - ecx) / ew;
        dy = (gcy - ecy) / eh;
        dw = logf(gw / ew);
        dh = logf(gh / eh);
        lbl = slab[bj];
        wgt = 1.0f;
    }

    // Layout: labels[N] | deltas[N][4] | bbwgts[N][1]
    out[ii] = lbl;
    reinterpret_cast<float4*>(out + N_ROIS)[ii] = make_float4(dx, dy, dw, dh);
    out[N_ROIS * 5 + ii] = wgt;
}

extern "C" void kernel_launch(void* const* d_in, const int* in_sizes, int n_in,
                              void* d_out, int out_size) {
    const float* rois = (const float*)d_in[0];
    const int*   rb   = (const int*)d_in[1];
    const float* gt   = (const float*)d_in[2];
    const int*   gb   = (const int*)d_in[3];
    float* out = (float*)d_out;

    roitarget_fused<<<NBLOCKS, NTHREADS>>>(rois, rb, gt, gb, out);
}